// round 12
// baseline (speedup 1.0000x reference)
#include <cuda_runtime.h>
#include <math.h>
#include <stdint.h>

// Problem constants
#define BZ   8
#define QL   2048
#define KL   2048
#define DIMH 128
#define SCALE 0.08838834764831845f
#define NT   256          // 8 warps: 2(M) x 4(N)

#define MASK_ELEMS (BZ * KL)

// strides (floats)
#define QLD 132
#define KLD 132
#define VLD 136

// ---------------- mask normalization (proven) -----------------------------
__device__ unsigned char g_mask[MASK_ELEMS];
__device__ int g_mask_kind;

__global__ void mask_detect_kernel(const unsigned int* __restrict__ mw) {
    __shared__ int not_int01, not_f01;
    if (threadIdx.x == 0) { not_int01 = 0; not_f01 = 0; }
    __syncthreads();
    int bad_i = 0, bad_f = 0;
    for (int i = threadIdx.x; i < 4096; i += blockDim.x) {
        unsigned int w = mw[i];
        if (w != 0u && w != 1u) bad_i = 1;
        if (w != 0u && w != 0x3F800000u) bad_f = 1;
    }
    if (bad_i) atomicExch(&not_int01, 1);
    if (bad_f) atomicExch(&not_f01, 1);
    __syncthreads();
    if (threadIdx.x == 0)
        g_mask_kind = (!not_int01) ? 1 : ((!not_f01) ? 2 : 0);
}

__global__ void mask_norm_kernel(const void* __restrict__ mraw) {
    int kind = g_mask_kind;
    int i = blockIdx.x * blockDim.x + threadIdx.x;
    if (i >= MASK_ELEMS) return;
    unsigned char m;
    if (kind == 1)      m = ((const int*)mraw)[i] != 0;
    else if (kind == 2) m = ((const float*)mraw)[i] != 0.0f;
    else                m = ((const unsigned char*)mraw)[i] != 0;
    g_mask[i] = m;
}

// ---------------- PTX helpers (non-arch-specific only) --------------------
__device__ __forceinline__ uint32_t tf32r(float x) {
    uint32_t r;
    asm("cvt.rna.tf32.f32 %0, %1;" : "=r"(r) : "f"(x));
    return r;
}

__device__ __forceinline__ void mma8(float& d0, float& d1, float& d2, float& d3,
                                     uint32_t a0, uint32_t a1, uint32_t a2, uint32_t a3,
                                     uint32_t b0, uint32_t b1) {
    asm volatile(
        "mma.sync.aligned.m16n8k8.row.col.f32.tf32.tf32.f32 "
        "{%0,%1,%2,%3}, {%4,%5,%6,%7}, {%8,%9}, {%0,%1,%2,%3};"
        : "+f"(d0), "+f"(d1), "+f"(d2), "+f"(d3)
        : "r"(a0), "r"(a1), "r"(a2), "r"(a3), "r"(b0), "r"(b1));
}

#define LDSM_X4(r0, r1, r2, r3, addr) \
    asm volatile("ldmatrix.sync.aligned.m8n8.x4.shared.b16 {%0,%1,%2,%3}, [%4];" \
        : "=r"(r0), "=r"(r1), "=r"(r2), "=r"(r3) : "r"(addr))

__device__ __forceinline__ uint32_t smem_u32(const void* p) {
    return (uint32_t)__cvta_generic_to_shared(p);
}

// ---------------- main kernel --------------------------------------------
// Grid (16,8) = 128 CTAs, 1 CTA/SM. Tile 128q x 128k, all tf32 (R5 numerics).
// 2-D warp tiling: 8 warps = 2(M) x 4(N/D); warp = 64 rows x 32 cols in both
// phases -> per-tile smem traffic 0.57x of R5. P overwrites K tile (extra sync).
// Fixed-max softmax p = exp(s*SCALE)*mask; O in registers across all tiles;
// cross-warp row-sum reduction once at the end.
__global__ void __launch_bounds__(NT, 1)
attn_mma_kernel(const float* __restrict__ q,
                const float* __restrict__ k,
                const float* __restrict__ v,
                float* __restrict__ out) {
    extern __shared__ float sm[];
    float* Qs   = sm;                     // 128 x QLD
    float* Ks   = Qs + 128 * QLD;         // 128 x KLD (becomes P)
    float* Vs   = Ks + 128 * KLD;         // 128 x VLD
    float* fmk  = Vs + 128 * VLD;         // 128
    float* lpart = fmk + 128;             // 4 x 128

    const int b     = blockIdx.y;
    const int qtile = blockIdx.x;
    const int t     = threadIdx.x;
    const int wid   = t >> 5;
    const int lane  = t & 31;
    const int g     = lane >> 2;
    const int tig   = lane & 3;

    const int wm    = wid & 1;        // M half (64 rows)
    const int wn    = wid >> 1;       // N quarter (S) / D quarter (PV)
    const int mrow0 = wm * 64;
    const int ncol0 = wn * 32;
    const int dcol0 = wn * 32;

    const float* qb = q + ((size_t)b * QL + (size_t)qtile * 128) * DIMH;
    const float* kb = k + (size_t)b * KL * DIMH;
    const float* vb = v + (size_t)b * KL * DIMH;
    const unsigned char* mb = g_mask + (size_t)b * KL;

    // ---- LDSM lane address components (32-bit data via b16 x4) ----
    // A frag (16x8 over floats): row = (L&7) + ((L>>3)&1)*8 ; colblk = (L>>4)*4
    const int a_r  = (lane & 7) + ((lane >> 3) & 1) * 8;
    const int a_c4 = (lane >> 4) * 4;
    // B frag x4 (two 8x8 n-blocks): row = (L>>4)*8 + (L&7) ; colblk = ((L>>3)&1)*4
    const int b_r  = ((lane >> 4) * 8) + (lane & 7);
    const int b_c4 = ((lane >> 3) & 1) * 4;

    uint32_t qA[4], kB[2], pA[4];
#pragma unroll
    for (int m2 = 0; m2 < 4; m2++) {
        qA[m2] = smem_u32(Qs + (mrow0 + 16 * m2 + a_r) * QLD + a_c4);
        pA[m2] = smem_u32(Ks + (mrow0 + 16 * m2 + a_r) * KLD + a_c4);
    }
#pragma unroll
    for (int nb = 0; nb < 2; nb++)
        kB[nb] = smem_u32(Ks + (ncol0 + nb * 16 + b_r) * KLD + b_c4);

    // ---- load Q tile once (tf32-rounded) ----
    for (int idx = t; idx < 4096; idx += NT) {
        int row = idx >> 5, c4 = idx & 31;
        float4 v4 = reinterpret_cast<const float4*>(qb)[idx];
        float* d = Qs + row * QLD + c4 * 4;
        d[0] = __uint_as_float(tf32r(v4.x));
        d[1] = __uint_as_float(tf32r(v4.y));
        d[2] = __uint_as_float(tf32r(v4.z));
        d[3] = __uint_as_float(tf32r(v4.w));
    }

    float oacc[4][4][4];
#pragma unroll
    for (int m2 = 0; m2 < 4; m2++)
#pragma unroll
        for (int n8 = 0; n8 < 4; n8++)
#pragma unroll
            for (int j = 0; j < 4; j++) oacc[m2][n8][j] = 0.0f;

    float rsum[8];
#pragma unroll
    for (int i = 0; i < 8; i++) rsum[i] = 0.0f;

    for (int kt = 0; kt < KL / 128; kt++) {
        __syncthreads();   // previous PV done before overwriting Ks(P)/Vs

        // ---- load K, V tiles (tf32-rounded) + mask ----
        const float* kp = kb + (size_t)kt * 128 * DIMH;
        const float* vp = vb + (size_t)kt * 128 * DIMH;
        for (int idx = t; idx < 4096; idx += NT) {
            int row = idx >> 5, c4 = idx & 31;
            float4 kv4 = reinterpret_cast<const float4*>(kp)[idx];
            float* dk = Ks + row * KLD + c4 * 4;
            dk[0] = __uint_as_float(tf32r(kv4.x));
            dk[1] = __uint_as_float(tf32r(kv4.y));
            dk[2] = __uint_as_float(tf32r(kv4.z));
            dk[3] = __uint_as_float(tf32r(kv4.w));
            float4 vv4 = reinterpret_cast<const float4*>(vp)[idx];
            float* dv = Vs + row * VLD + c4 * 4;
            dv[0] = __uint_as_float(tf32r(vv4.x));
            dv[1] = __uint_as_float(tf32r(vv4.y));
            dv[2] = __uint_as_float(tf32r(vv4.z));
            dv[3] = __uint_as_float(tf32r(vv4.w));
        }
        if (t < 128) fmk[t] = (float)mb[(size_t)kt * 128 + t];
        __syncthreads();

        // ---- S = Q @ K^T  (tf32, 16 k8-chunks) ----
        float sacc[4][4][4];
#pragma unroll
        for (int m2 = 0; m2 < 4; m2++)
#pragma unroll
            for (int n8 = 0; n8 < 4; n8++)
#pragma unroll
                for (int j = 0; j < 4; j++) sacc[m2][n8][j] = 0.0f;

#pragma unroll 2
        for (int kc = 0; kc < 16; kc++) {
            uint32_t a[4][4];
#pragma unroll
            for (int m2 = 0; m2 < 4; m2++)
                LDSM_X4(a[m2][0], a[m2][1], a[m2][2], a[m2][3], qA[m2] + kc * 32);
#pragma unroll
            for (int nb = 0; nb < 2; nb++) {
                uint32_t b0, b1, c0, c1;
                LDSM_X4(b0, b1, c0, c1, kB[nb] + kc * 32);
#pragma unroll
                for (int m2 = 0; m2 < 4; m2++) {
                    mma8(sacc[m2][2 * nb][0], sacc[m2][2 * nb][1],
                         sacc[m2][2 * nb][2], sacc[m2][2 * nb][3],
                         a[m2][0], a[m2][1], a[m2][2], a[m2][3], b0, b1);
                    mma8(sacc[m2][2 * nb + 1][0], sacc[m2][2 * nb + 1][1],
                         sacc[m2][2 * nb + 1][2], sacc[m2][2 * nb + 1][3],
                         a[m2][0], a[m2][1], a[m2][2], a[m2][3], c0, c1);
                }
            }
        }
        __syncthreads();   // everyone done reading K before P overwrites it

        // ---- softmax: p = exp(s*SCALE)*mask; write P (tf32) into Ks ----
#pragma unroll
        for (int m2 = 0; m2 < 4; m2++) {
            int r0 = mrow0 + 16 * m2 + g;
#pragma unroll
            for (int n8 = 0; n8 < 4; n8++) {
                int cbase = ncol0 + n8 * 8 + 2 * tig;
                float fm0 = fmk[cbase], fm1 = fmk[cbase + 1];
                float p0 = __expf(sacc[m2][n8][0] * SCALE) * fm0;
                float p1 = __expf(sacc[m2][n8][1] * SCALE) * fm1;
                float p2 = __expf(sacc[m2][n8][2] * SCALE) * fm0;
                float p3 = __expf(sacc[m2][n8][3] * SCALE) * fm1;
                rsum[2 * m2]     += p0 + p1;
                rsum[2 * m2 + 1] += p2 + p3;
                float2 w0 = make_float2(__uint_as_float(tf32r(p0)), __uint_as_float(tf32r(p1)));
                float2 w1 = make_float2(__uint_as_float(tf32r(p2)), __uint_as_float(tf32r(p3)));
                *reinterpret_cast<float2*>(Ks + r0 * KLD + cbase)       = w0;
                *reinterpret_cast<float2*>(Ks + (r0 + 8) * KLD + cbase) = w1;
            }
        }
        __syncthreads();   // P fully visible

        // ---- O += P @ V  (tf32, 16 k8-chunks; B scalar LDS) ----
#pragma unroll 2
        for (int kc = 0; kc < 16; kc++) {
            uint32_t a[4][4];
#pragma unroll
            for (int m2 = 0; m2 < 4; m2++)
                LDSM_X4(a[m2][0], a[m2][1], a[m2][2], a[m2][3], pA[m2] + kc * 32);
            const float* vr0 = Vs + (8 * kc + tig) * VLD + dcol0 + g;
            const float* vr1 = vr0 + 4 * VLD;
#pragma unroll
            for (int n8 = 0; n8 < 4; n8++) {
                uint32_t b0 = __float_as_uint(vr0[n8 * 8]);
                uint32_t b1 = __float_as_uint(vr1[n8 * 8]);
#pragma unroll
                for (int m2 = 0; m2 < 4; m2++)
                    mma8(oacc[m2][n8][0], oacc[m2][n8][1], oacc[m2][n8][2], oacc[m2][n8][3],
                         a[m2][0], a[m2][1], a[m2][2], a[m2][3], b0, b1);
            }
        }
    }

    // ---- reduce row sums: quad shfl, then across 4 N-warps via smem ----
#pragma unroll
    for (int i = 0; i < 8; i++) {
        rsum[i] += __shfl_xor_sync(0xFFFFFFFFu, rsum[i], 1);
        rsum[i] += __shfl_xor_sync(0xFFFFFFFFu, rsum[i], 2);
    }
    if (tig == 0) {
#pragma unroll
        for (int m2 = 0; m2 < 4; m2++) {
            int r0 = mrow0 + 16 * m2 + g;
            lpart[wn * 128 + r0]     = rsum[2 * m2];
            lpart[wn * 128 + r0 + 8] = rsum[2 * m2 + 1];
        }
    }
    __syncthreads();

    // ---- scale + store ----
    const size_t obase = ((size_t)b * QL + (size_t)qtile * 128) * DIMH;
#pragma unroll
    for (int m2 = 0; m2 < 4; m2++) {
        int r0 = mrow0 + 16 * m2 + g;
        int r1 = r0 + 8;
        float inv0 = 1.0f / (lpart[r0] + lpart[128 + r0] + lpart[256 + r0] + lpart[384 + r0]);
        float inv1 = 1.0f / (lpart[r1] + lpart[128 + r1] + lpart[256 + r1] + lpart[384 + r1]);
        float* or0 = out + obase + (size_t)r0 * DIMH;
        float* or1 = out + obase + (size_t)r1 * DIMH;
#pragma unroll
        for (int n8 = 0; n8 < 4; n8++) {
            float2 w0 = make_float2(oacc[m2][n8][0] * inv0, oacc[m2][n8][1] * inv0);
            float2 w1 = make_float2(oacc[m2][n8][2] * inv1, oacc[m2][n8][3] * inv1);
            reinterpret_cast<float2*>(or0)[dcol0 / 2 + n8 * 4 + tig] = w0;
            reinterpret_cast<float2*>(or1)[dcol0 / 2 + n8 * 4 + tig] = w1;
        }
    }
}

extern "C" void kernel_launch(void* const* d_in, const int* in_sizes, int n_in,
                              void* d_out, int out_size) {
    const float* q = (const float*)d_in[0];
    const float* k = (const float*)d_in[1];
    const float* v = (const float*)d_in[2];
    const void*  mraw = d_in[3];
    float* out = (float*)d_out;

    mask_detect_kernel<<<1, 256>>>((const unsigned int*)mraw);
    mask_norm_kernel<<<(MASK_ELEMS + 255) / 256, 256>>>(mraw);

    const int smem_floats = 128 * QLD + 128 * KLD + 128 * VLD + 128 + 512;
    const int smem_bytes  = smem_floats * 4;
    cudaFuncSetAttribute(attn_mma_kernel, cudaFuncAttributeMaxDynamicSharedMemorySize, smem_bytes);

    dim3 grid(QL / 128, BZ);
    attn_mma_kernel<<<grid, NT, smem_bytes>>>(q, k, v, out);
}

// round 14
// speedup vs baseline: 2.2914x; 2.2914x over previous
#include <cuda_runtime.h>
#include <cuda_fp16.h>
#include <math.h>
#include <stdint.h>

// Problem constants
#define BZ   8
#define QL   2048
#define KL   2048
#define DIMH 128
#define SCALE 0.08838834764831845f
#define NT   256          // 8 warps x 16 q-rows (R5 1-D tiling)

#define MASK_ELEMS (BZ * KL)

// half strides per row (136 halfs = 272B; 68 words = 4 mod 32 -> LDSM-phase
// conflict-free for all fragment patterns used below)
#define QLDH 136
#define KLDH 136
#define VLDH 136
#define PLDH 136

// ---------------- mask normalization (proven) -----------------------------
__device__ unsigned char g_mask[MASK_ELEMS];
__device__ int g_mask_kind;

__global__ void mask_detect_kernel(const unsigned int* __restrict__ mw) {
    __shared__ int not_int01, not_f01;
    if (threadIdx.x == 0) { not_int01 = 0; not_f01 = 0; }
    __syncthreads();
    int bad_i = 0, bad_f = 0;
    for (int i = threadIdx.x; i < 4096; i += blockDim.x) {
        unsigned int w = mw[i];
        if (w != 0u && w != 1u) bad_i = 1;
        if (w != 0u && w != 0x3F800000u) bad_f = 1;
    }
    if (bad_i) atomicExch(&not_int01, 1);
    if (bad_f) atomicExch(&not_f01, 1);
    __syncthreads();
    if (threadIdx.x == 0)
        g_mask_kind = (!not_int01) ? 1 : ((!not_f01) ? 2 : 0);
}

__global__ void mask_norm_kernel(const void* __restrict__ mraw) {
    int kind = g_mask_kind;
    int i = blockIdx.x * blockDim.x + threadIdx.x;
    if (i >= MASK_ELEMS) return;
    unsigned char m;
    if (kind == 1)      m = ((const int*)mraw)[i] != 0;
    else if (kind == 2) m = ((const float*)mraw)[i] != 0.0f;
    else                m = ((const unsigned char*)mraw)[i] != 0;
    g_mask[i] = m;
}

// ---------------- PTX helpers (non-arch-specific only) --------------------
__device__ __forceinline__ void mma16(float& d0, float& d1, float& d2, float& d3,
                                      uint32_t a0, uint32_t a1, uint32_t a2, uint32_t a3,
                                      uint32_t b0, uint32_t b1) {
    asm volatile(
        "mma.sync.aligned.m16n8k16.row.col.f32.f16.f16.f32 "
        "{%0,%1,%2,%3}, {%4,%5,%6,%7}, {%8,%9}, {%0,%1,%2,%3};"
        : "+f"(d0), "+f"(d1), "+f"(d2), "+f"(d3)
        : "r"(a0), "r"(a1), "r"(a2), "r"(a3), "r"(b0), "r"(b1));
}

#define LDSM_X4(r0, r1, r2, r3, addr) \
    asm volatile("ldmatrix.sync.aligned.m8n8.x4.shared.b16 {%0,%1,%2,%3}, [%4];" \
        : "=r"(r0), "=r"(r1), "=r"(r2), "=r"(r3) : "r"(addr))

#define LDSM_X4_T(r0, r1, r2, r3, addr) \
    asm volatile("ldmatrix.sync.aligned.m8n8.x4.trans.shared.b16 {%0,%1,%2,%3}, [%4];" \
        : "=r"(r0), "=r"(r1), "=r"(r2), "=r"(r3) : "r"(addr))

__device__ __forceinline__ uint32_t smem_u32(const void* p) {
    return (uint32_t)__cvta_generic_to_shared(p);
}

// ---------------- main kernel --------------------------------------------
// Grid (16,8) = 128 CTAs, 1 CTA/SM. Tile 128q x 128k, all fp16 inputs
// (11-bit mantissa = tf32), fp32 accumulate. R5's proven 1-D warp tiling:
// warp = 16 q-rows x full 128 cols in both phases. V fed via ldmatrix.trans
// (no scalar LDS). P in its own buffer -> warp-private -> 2 barriers/tile.
// Fixed-max softmax p = exp(s*SCALE)*mask; O in registers across all tiles.
__global__ void __launch_bounds__(NT, 1)
attn_mma_kernel(const float* __restrict__ q,
                const float* __restrict__ k,
                const float* __restrict__ v,
                float* __restrict__ out) {
    extern __shared__ char smraw[];
    __half* Qh = reinterpret_cast<__half*>(smraw);
    __half* Kh = Qh + 128 * QLDH;
    __half* Vh = Kh + 128 * KLDH;
    __half* Ph = Vh + 128 * VLDH;
    float*  fmk = reinterpret_cast<float*>(Ph + 128 * PLDH);

    const int b     = blockIdx.y;
    const int qtile = blockIdx.x;
    const int t     = threadIdx.x;
    const int wid   = t >> 5;
    const int lane  = t & 31;
    const int g     = lane >> 2;
    const int tig   = lane & 3;
    const int m0    = wid * 16;

    const float* qb = q + ((size_t)b * QL + (size_t)qtile * 128) * DIMH;
    const float* kb = k + (size_t)b * KL * DIMH;
    const float* vb = v + (size_t)b * KL * DIMH;
    const unsigned char* mb = g_mask + (size_t)b * KL;

    // ---- LDSM lane addresses (byte) ----
    // A-frag x4 (Q/P): row = (L&7)+8*((L>>3)&1), colhalf = 8*(L>>4)
    const int a_r  = (lane & 7) + 8 * ((lane >> 3) & 1);
    const int a_ch = 8 * (lane >> 4);
    // K-as-B x4: row = n0 + (L&7) + 8*(L>>4), colhalf = 8*((L>>3)&1)
    const int kb_r = (lane & 7) + 8 * (lane >> 4);
    const int kb_ch = 8 * ((lane >> 3) & 1);
    // V-as-B x4 trans: row = k0 + (L&7)+8*((L>>3)&1), colhalf = d0 + 8*(L>>4)
    const int vb_r  = (lane & 7) + 8 * ((lane >> 3) & 1);
    const int vb_ch = 8 * (lane >> 4);

    const uint32_t qA = smem_u32(Qh + (m0 + a_r) * QLDH + a_ch);
    const uint32_t pA = smem_u32(Ph + (m0 + a_r) * PLDH + a_ch);
    uint32_t kB[8];
#pragma unroll
    for (int nb = 0; nb < 8; nb++)
        kB[nb] = smem_u32(Kh + (16 * nb + kb_r) * KLDH + kb_ch);
    const uint32_t vB0 = smem_u32(Vh + vb_r * VLDH + vb_ch);

    // ---- load Q tile once (fp16) ----
    for (int idx = t; idx < 4096; idx += NT) {
        int row = idx >> 5, c4 = idx & 31;
        float4 v4 = reinterpret_cast<const float4*>(qb)[idx];
        __half2 h0 = __floats2half2_rn(v4.x, v4.y);
        __half2 h1 = __floats2half2_rn(v4.z, v4.w);
        uint2 pk;
        pk.x = *reinterpret_cast<uint32_t*>(&h0);
        pk.y = *reinterpret_cast<uint32_t*>(&h1);
        *reinterpret_cast<uint2*>(Qh + row * QLDH + c4 * 4) = pk;
    }

    float oacc[16][4];
#pragma unroll
    for (int n = 0; n < 16; n++)
#pragma unroll
        for (int j = 0; j < 4; j++) oacc[n][j] = 0.0f;

    float rs0 = 0.0f, rs1 = 0.0f;

    for (int kt = 0; kt < KL / 128; kt++) {
        __syncthreads();   // everyone done with Kh/Vh before overwrite

        // ---- load K, V tiles (fp16) + mask ----
        const float* kp = kb + (size_t)kt * 128 * DIMH;
        const float* vp = vb + (size_t)kt * 128 * DIMH;
        for (int idx = t; idx < 4096; idx += NT) {
            int row = idx >> 5, c4 = idx & 31;
            float4 kv4 = reinterpret_cast<const float4*>(kp)[idx];
            __half2 k0 = __floats2half2_rn(kv4.x, kv4.y);
            __half2 k1 = __floats2half2_rn(kv4.z, kv4.w);
            uint2 pk;
            pk.x = *reinterpret_cast<uint32_t*>(&k0);
            pk.y = *reinterpret_cast<uint32_t*>(&k1);
            *reinterpret_cast<uint2*>(Kh + row * KLDH + c4 * 4) = pk;
            float4 vv4 = reinterpret_cast<const float4*>(vp)[idx];
            __half2 v0 = __floats2half2_rn(vv4.x, vv4.y);
            __half2 v1 = __floats2half2_rn(vv4.z, vv4.w);
            uint2 pv;
            pv.x = *reinterpret_cast<uint32_t*>(&v0);
            pv.y = *reinterpret_cast<uint32_t*>(&v1);
            *reinterpret_cast<uint2*>(Vh + row * VLDH + c4 * 4) = pv;
        }
        if (t < 128) fmk[t] = (float)mb[(size_t)kt * 128 + t];
        __syncthreads();

        // ---- S = Q @ K^T  (fp16 k16, 8 chunks) ----
        float sacc[16][4];
#pragma unroll
        for (int n = 0; n < 16; n++)
#pragma unroll
            for (int j = 0; j < 4; j++) sacc[n][j] = 0.0f;

#pragma unroll 2
        for (int kc = 0; kc < 8; kc++) {
            uint32_t a0, a1, a2, a3;
            LDSM_X4(a0, a1, a2, a3, qA + kc * 32);
#pragma unroll
            for (int nb = 0; nb < 8; nb++) {
                uint32_t b0, b1, c0, c1;
                LDSM_X4(b0, b1, c0, c1, kB[nb] + kc * 32);
                mma16(sacc[2 * nb][0], sacc[2 * nb][1], sacc[2 * nb][2], sacc[2 * nb][3],
                      a0, a1, a2, a3, b0, b1);
                mma16(sacc[2 * nb + 1][0], sacc[2 * nb + 1][1],
                      sacc[2 * nb + 1][2], sacc[2 * nb + 1][3],
                      a0, a1, a2, a3, c0, c1);
            }
        }

        // ---- softmax: p = exp(s*SCALE)*mask; write P (fp16, warp-private) ----
        {
            __half* pr0 = Ph + (m0 + g) * PLDH;
            __half* pr1 = Ph + (m0 + g + 8) * PLDH;
#pragma unroll
            for (int n = 0; n < 16; n++) {
                int col = 8 * n + 2 * tig;
                float fm0 = fmk[col], fm1 = fmk[col + 1];
                float p0 = __expf(sacc[n][0] * SCALE) * fm0;
                float p1 = __expf(sacc[n][1] * SCALE) * fm1;
                float p2 = __expf(sacc[n][2] * SCALE) * fm0;
                float p3 = __expf(sacc[n][3] * SCALE) * fm1;
                rs0 += p0 + p1;
                rs1 += p2 + p3;
                *reinterpret_cast<__half2*>(pr0 + col) = __floats2half2_rn(p0, p1);
                *reinterpret_cast<__half2*>(pr1 + col) = __floats2half2_rn(p2, p3);
            }
        }
        // no barrier: P rows are written and read by the same warp

        // ---- O += P @ V  (fp16 k16; V via ldmatrix.trans) ----
#pragma unroll 2
        for (int kc = 0; kc < 8; kc++) {
            uint32_t a0, a1, a2, a3;
            LDSM_X4(a0, a1, a2, a3, pA + kc * 32);
            uint32_t vbase = vB0 + kc * (16 * VLDH * 2);
#pragma unroll
            for (int db = 0; db < 8; db++) {
                uint32_t b0, b1, c0, c1;
                LDSM_X4_T(b0, b1, c0, c1, vbase + db * 32);
                mma16(oacc[2 * db][0], oacc[2 * db][1], oacc[2 * db][2], oacc[2 * db][3],
                      a0, a1, a2, a3, b0, b1);
                mma16(oacc[2 * db + 1][0], oacc[2 * db + 1][1],
                      oacc[2 * db + 1][2], oacc[2 * db + 1][3],
                      a0, a1, a2, a3, c0, c1);
            }
        }
    }

    // ---- finalize: reduce row sums across the quad, scale, store ----
    rs0 += __shfl_xor_sync(0xFFFFFFFFu, rs0, 1);
    rs0 += __shfl_xor_sync(0xFFFFFFFFu, rs0, 2);
    rs1 += __shfl_xor_sync(0xFFFFFFFFu, rs1, 1);
    rs1 += __shfl_xor_sync(0xFFFFFFFFu, rs1, 2);
    float inv0 = 1.0f / rs0;
    float inv1 = 1.0f / rs1;

    float* or0 = out + ((size_t)b * QL + (size_t)qtile * 128 + m0 + g) * DIMH;
    float* or1 = or0 + 8 * DIMH;
#pragma unroll
    for (int n = 0; n < 16; n++) {
        float2 w0 = make_float2(oacc[n][0] * inv0, oacc[n][1] * inv0);
        float2 w1 = make_float2(oacc[n][2] * inv1, oacc[n][3] * inv1);
        reinterpret_cast<float2*>(or0)[4 * n + tig] = w0;
        reinterpret_cast<float2*>(or1)[4 * n + tig] = w1;
    }
}

extern "C" void kernel_launch(void* const* d_in, const int* in_sizes, int n_in,
                              void* d_out, int out_size) {
    const float* q = (const float*)d_in[0];
    const float* k = (const float*)d_in[1];
    const float* v = (const float*)d_in[2];
    const void*  mraw = d_in[3];
    float* out = (float*)d_out;

    mask_detect_kernel<<<1, 256>>>((const unsigned int*)mraw);
    mask_norm_kernel<<<(MASK_ELEMS + 255) / 256, 256>>>(mraw);

    const int smem_bytes = (128 * QLDH + 128 * KLDH + 128 * VLDH + 128 * PLDH) * 2
                         + 128 * 4;
    cudaFuncSetAttribute(attn_mma_kernel, cudaFuncAttributeMaxDynamicSharedMemorySize, smem_bytes);

    dim3 grid(QL / 128, BZ);
    attn_mma_kernel<<<grid, NT, smem_bytes>>>(q, k, v, out);
}